// round 16
// baseline (speedup 1.0000x reference)
#include <cuda_runtime.h>
#include <cuda_fp16.h>
#include <math.h>
#include <stdint.h>

// ---------------- problem constants ----------------
#define BB   2
#define SS   4096
#define HIDN 2048
#define NH   16
#define HD   128
#define CC   256
#define NCC  16
#define MM   (BB*SS)          // 8192
#define QKVN (3*HIDN)         // 6144
#define GK   HIDN
#define BKC  64
#define NCHUNK (GK/BKC)       // 32

// ---------------- device scratch ----------------
__device__ float g_kvdelta[(size_t)BB*NH*NCC*HD*HD];
__device__ float g_kvstate[(size_t)BB*NH*NCC*HD*HD];

__device__ __half g_qkv16[(size_t)MM * QKVN];      // linear [M, 6144] fp16
__device__ __half g_x16[(size_t)MM*HIDN];
__device__ __half g_wqkvT_h[(size_t)QKVN*HIDN];
__device__ __half g_wgateT_h[(size_t)HIDN*HIDN];
__device__ __half g_woutT_h[(size_t)HIDN*HIDN];
__device__ __half g_ga16[(size_t)MM*HIDN];
__device__ __half g_gate16[(size_t)MM*HIDN];

#define PHSZ ((size_t)BB*NH*SS*HD)
__device__ __half g_kdT [PHSZ];                    // [bh][d][s]
__device__ __half g_vT  [PHSZ];                    // [bh][d][s]
__device__ __half g_kvsT[(size_t)BB*NH*NCC*HD*HD]; // [bhn][e][d']
__device__ float g_qdectab[NH*CC], g_kdectab[NH*CC];

// ---------------- epilogues ----------------
#define EPI_SILU    0
#define EPI_SIGMOID 1
#define EPI_NONE    2

__device__ __forceinline__ float apply_epi(float x, int mode) {
    if (mode == EPI_SILU)    return x / (1.0f + expf(-x));
    if (mode == EPI_SIGMOID) return 1.0f / (1.0f + expf(-x));
    return x;
}

// ---------------- base-ISA tensor-core helpers ----------------
__device__ __forceinline__ uint32_t smem_u32(const void* p) {
    uint32_t a;
    asm("{ .reg .u64 t; cvta.to.shared.u64 t, %1; cvt.u32.u64 %0, t; }" : "=r"(a) : "l"(p));
    return a;
}
__device__ __forceinline__ void cpasync16(uint32_t saddr, const void* g) {
    asm volatile("cp.async.cg.shared.global [%0], [%1], 16;" :: "r"(saddr), "l"(g));
}
__device__ __forceinline__ void cp_commit() {
    asm volatile("cp.async.commit_group;" ::: "memory");
}
template<int N> __device__ __forceinline__ void cp_wait() {
    asm volatile("cp.async.wait_group %0;" :: "n"(N) : "memory");
}
__device__ __forceinline__ void ldm_x4(uint32_t* r, uint32_t addr) {
    asm volatile("ldmatrix.sync.aligned.m8n8.x4.shared.b16 {%0,%1,%2,%3}, [%4];"
                 : "=r"(r[0]), "=r"(r[1]), "=r"(r[2]), "=r"(r[3]) : "r"(addr));
}
__device__ __forceinline__ void ldm_x2(uint32_t* r, uint32_t addr) {
    asm volatile("ldmatrix.sync.aligned.m8n8.x2.shared.b16 {%0,%1}, [%2];"
                 : "=r"(r[0]), "=r"(r[1]) : "r"(addr));
}
__device__ __forceinline__ void mma16816h(float* c, const uint32_t* a, const uint32_t* b) {
    asm volatile(
        "mma.sync.aligned.m16n8k16.row.col.f32.f16.f16.f32 "
        "{%0,%1,%2,%3},{%4,%5,%6,%7},{%8,%9},{%0,%1,%2,%3};"
        : "+f"(c[0]), "+f"(c[1]), "+f"(c[2]), "+f"(c[3])
        : "r"(a[0]), "r"(a[1]), "r"(a[2]), "r"(a[3]), "r"(b[0]), "r"(b[1]));
}

#define LDSW   144

// ---------------- fp16 1-pass GEMM: tile 128x256, 512 thr ----------------
// B/C may be pre-offset by a column base; N is the store row-stride.
#define HA_SZ  (128 * LDSW)               // 18432
#define HB_SZ  (256 * LDSW)               // 36864
#define H1BUF  (HA_SZ + HB_SZ)            // 55296
#define GEMM1_SMEM (2 * H1BUF)            // 110592

template<int EPI, bool OUT16>
__global__ __launch_bounds__(512) void mma_gemm_1(
    const __half* __restrict__ A, const __half* __restrict__ Bh,
    float* __restrict__ Cf, __half* __restrict__ Ch, int M, int N)
{
    extern __shared__ char smraw[];
    const uint32_t sb = smem_u32(smraw);

    const int tid  = threadIdx.x;
    const int lane = tid & 31;
    const int wid  = tid >> 5;
    const int bm = blockIdx.y * 128;
    const int bn = blockIdx.x * 256;
    const int wm = (wid >> 3) * 64;
    const int wn = (wid & 7) * 32;

    auto prefetch = [&](int c, int buf) {
        const uint32_t bbase = sb + buf * H1BUF;
        const int k0 = c * BKC;
        #pragma unroll
        for (int i = 0; i < 2; ++i) {
            int idx = tid + 512 * i;
            int row = idx >> 3, sec = idx & 7;
            const uint32_t so = row * LDSW + sec * 16;
            const size_t ga = (size_t)(bm + row) * GK + k0 + sec * 8;
            cpasync16(bbase + so, A + ga);
        }
        #pragma unroll
        for (int i = 0; i < 4; ++i) {
            int idx = tid + 512 * i;
            int row = idx >> 3, sec = idx & 7;
            const uint32_t so = row * LDSW + sec * 16;
            const size_t gb = (size_t)(bn + row) * GK + k0 + sec * 8;
            cpasync16(bbase + HA_SZ + so, Bh + gb);
        }
        cp_commit();
    };

    float acc[4][4][4];
    #pragma unroll
    for (int mi = 0; mi < 4; ++mi)
        #pragma unroll
        for (int ni = 0; ni < 4; ++ni)
            #pragma unroll
            for (int r = 0; r < 4; ++r) acc[mi][ni][r] = 0.0f;

    const uint32_t aOff = (uint32_t)(wm + (lane & 15)) * LDSW + (lane >> 4) * 16;
    const uint32_t bOff = (uint32_t)(wn + (lane & 7))  * LDSW + ((lane >> 3) & 1) * 16;

    prefetch(0, 0);

    for (int c = 0; c < NCHUNK; ++c) {
        const int cur = c & 1;
        if (c + 1 < NCHUNK) prefetch(c + 1, cur ^ 1);
        if (c + 1 < NCHUNK) cp_wait<1>(); else cp_wait<0>();
        __syncthreads();

        const uint32_t bbase = sb + cur * H1BUF;
        #pragma unroll
        for (int ks = 0; ks < 4; ++ks) {
            const uint32_t kso = ks * 32;
            uint32_t aF[4][4], bF[4][2];
            #pragma unroll
            for (int mi = 0; mi < 4; ++mi)
                ldm_x4(aF[mi], bbase + aOff + mi * 16 * LDSW + kso);
            #pragma unroll
            for (int ni = 0; ni < 4; ++ni)
                ldm_x2(bF[ni], bbase + HA_SZ + bOff + ni * 8 * LDSW + kso);
            #pragma unroll
            for (int mi = 0; mi < 4; ++mi)
                #pragma unroll
                for (int ni = 0; ni < 4; ++ni)
                    mma16816h(acc[mi][ni], aF[mi], bF[ni]);
        }
        __syncthreads();
    }

    const int erow = lane >> 2;
    const int ecol = 2 * (lane & 3);
    #pragma unroll
    for (int mi = 0; mi < 4; ++mi) {
        #pragma unroll
        for (int ni = 0; ni < 4; ++ni) {
            const int gr0 = bm + wm + mi * 16 + erow;
            const int gc  = bn + wn + ni * 8 + ecol;
            float v0 = apply_epi(acc[mi][ni][0], EPI);
            float v1 = apply_epi(acc[mi][ni][1], EPI);
            float v2 = apply_epi(acc[mi][ni][2], EPI);
            float v3 = apply_epi(acc[mi][ni][3], EPI);
            if (OUT16) {
                size_t o0 = (size_t)gr0 * N + gc;
                *(__half2*)(Ch + o0) =
                    __halves2half2(__float2half(v0), __float2half(v1));
                *(__half2*)(Ch + o0 + 8 * (size_t)N) =
                    __halves2half2(__float2half(v2), __float2half(v3));
            } else {
                *(float2*)(Cf + (size_t)gr0 * N + gc)       = make_float2(v0, v1);
                *(float2*)(Cf + (size_t)(gr0 + 8) * N + gc) = make_float2(v2, v3);
            }
        }
    }
}

// ---------------- conversion kernels ----------------
__device__ __forceinline__ void store4h(__half* d, size_t o, float4 v)
{
    *(__half2*)(d + o)     = __halves2half2(__float2half(v.x), __float2half(v.y));
    *(__half2*)(d + o + 2) = __halves2half2(__float2half(v.z), __float2half(v.w));
}

__global__ __launch_bounds__(256) void tohalf_kernel(
    const float* __restrict__ in, __half* __restrict__ d16, int n4)
{
    int i = blockIdx.x * 256 + threadIdx.x;
    if (i >= n4) return;
    store4h(d16, (size_t)i * 4, ((const float4*)in)[i]);
}

__global__ void transp_half_kernel(
    const float* __restrict__ w, __half* __restrict__ t, int K, int N)
{
    __shared__ float ts[32][33];
    const int n0 = blockIdx.x * 32, k0 = blockIdx.y * 32;
    const int x = threadIdx.x, y = threadIdx.y;
    #pragma unroll
    for (int r = 0; r < 32; r += 8)
        ts[y + r][x] = w[(size_t)(k0 + y + r) * N + n0 + x];
    __syncthreads();
    #pragma unroll
    for (int r = 0; r < 32; r += 8) {
        size_t o = (size_t)(n0 + y + r) * K + k0 + x;
        t[o] = __float2half(ts[x][y + r]);
    }
}

__global__ void dectab_kernel(const float* __restrict__ slopes)
{
    int h = blockIdx.x, i = threadIdx.x;
    float s = slopes[h];
    g_qdectab[h * CC + i] = expf(-s * (float)(i + 1));
    g_kdectab[h * CC + i] = expf(-s * (float)(CC - 1 - i));
}

// g_qkv16 k,v -> kdT (decayed), vT [bh][d][s] fp16
__global__ void trans_split_head()
{
    __shared__ float tk[32][33], tv[32][33];
    const int z  = blockIdx.z;
    const int b  = z >> 4, h = z & 15;
    const int s0 = blockIdx.x * 32;
    const int d0 = blockIdx.y * 32;
    const int x = threadIdx.x, y = threadIdx.y;

    #pragma unroll
    for (int r = 0; r < 32; r += 8) {
        size_t base = (size_t)(b * SS + s0 + y + r) * QKVN + h * HD + d0 + x;
        tk[y + r][x] = __half2float(g_qkv16[base + HIDN]);
        tv[y + r][x] = __half2float(g_qkv16[base + 2 * HIDN]);
    }
    __syncthreads();
    #pragma unroll
    for (int r = 0; r < 32; r += 8) {
        int d = d0 + y + r;
        int s = s0 + x;
        float kdec = g_kdectab[h * CC + (s & (CC - 1))];
        size_t o = ((size_t)z * HD + d) * SS + s;
        g_kdT[o] = __float2half(tk[x][y + r] * kdec);
        g_vT[o]  = __float2half(tv[x][y + r]);
    }
}

// g_kvstate [bhn][d'][e] -> kvsT [bhn][e][d'] fp16
__global__ void kvsplitT_kernel()
{
    __shared__ float t[32][33];
    const int bhn = blockIdx.z;
    const int d0 = blockIdx.x * 32;
    const int e0 = blockIdx.y * 32;
    const int x = threadIdx.x, y = threadIdx.y;
    const size_t base = (size_t)bhn * HD * HD;

    #pragma unroll
    for (int r = 0; r < 32; r += 8)
        t[y + r][x] = g_kvstate[base + (size_t)(d0 + y + r) * HD + e0 + x];
    __syncthreads();
    #pragma unroll
    for (int r = 0; r < 32; r += 8) {
        size_t o = base + (size_t)(e0 + y + r) * HD + d0 + x;
        g_kvsT[o] = __float2half(t[x][y + r]);
    }
}

// ---------------- kvdelta via HMMA (fp16 1-pass, double-buffered) ----------------
#define KD_MAT  18432
#define KD_BUF  (2 * KD_MAT)          // 36864
#define KD_SMEM (2 * KD_BUF)          // 73728

__global__ __launch_bounds__(256) void kvdelta_mma()
{
    extern __shared__ char smraw[];
    const uint32_t sb = smem_u32(smraw);

    const int blk = blockIdx.x;
    const int n  = blk & (NCC - 1);
    const int bh = blk >> 4;
    const size_t colb = (size_t)bh * HD;

    const int tid = threadIdx.x, lane = tid & 31, wid = tid >> 5;
    const int wm = (wid >> 2) * 64;
    const int wn = (wid & 3) * 32;

    auto prefetch = [&](int kt, int buf) {
        const uint32_t bbase = sb + buf * KD_BUF;
        const int k0 = n * CC + kt * 64;
        #pragma unroll
        for (int it = 0; it < 4; ++it) {
            int idx = tid + 256 * it;
            int row = idx >> 3, sec = idx & 7;
            size_t g = (colb + row) * SS + k0 + sec * 8;
            uint32_t so = row * 144 + sec * 16;
            cpasync16(bbase + 0 * KD_MAT + so, g_kdT + g);
            cpasync16(bbase + 1 * KD_MAT + so, g_vT + g);
        }
        cp_commit();
    };

    float acc[4][4][4];
    #pragma unroll
    for (int mi = 0; mi < 4; ++mi)
        #pragma unroll
        for (int ni = 0; ni < 4; ++ni)
            #pragma unroll
            for (int r = 0; r < 4; ++r) acc[mi][ni][r] = 0.0f;

    prefetch(0, 0);

    for (int kt = 0; kt < 4; ++kt) {
        const int cur = kt & 1;
        if (kt + 1 < 4) prefetch(kt + 1, cur ^ 1);
        if (kt + 1 < 4) cp_wait<1>(); else cp_wait<0>();
        __syncthreads();

        const uint32_t bbase = sb + cur * KD_BUF;
        #pragma unroll
        for (int ks = 0; ks < 4; ++ks) {
            uint32_t aF[4][4], bF[4][2];
            const uint32_t ao = (uint32_t)(lane & 15) * 144 + (lane >> 4) * 16 + ks * 32;
            #pragma unroll
            for (int mi = 0; mi < 4; ++mi)
                ldm_x4(aF[mi], bbase + 0 * KD_MAT + (wm + mi * 16) * 144 + ao);
            const uint32_t bo = (uint32_t)(lane & 7) * 144 + ((lane >> 3) & 1) * 16 + ks * 32;
            #pragma unroll
            for (int ni = 0; ni < 4; ++ni)
                ldm_x2(bF[ni], bbase + 1 * KD_MAT + (wn + ni * 8) * 144 + bo);
            #pragma unroll
            for (int mi = 0; mi < 4; ++mi)
                #pragma unroll
                for (int ni = 0; ni < 4; ++ni)
                    mma16816h(acc[mi][ni], aF[mi], bF[ni]);
        }
        __syncthreads();
    }

    const int erow = lane >> 2, ecol = 2 * (lane & 3);
    float* out = &g_kvdelta[(size_t)blk * HD * HD];
    #pragma unroll
    for (int mi = 0; mi < 4; ++mi) {
        #pragma unroll
        for (int ni = 0; ni < 4; ++ni) {
            int d = wm + mi * 16 + erow;
            int e = wn + ni * 8 + ecol;
            *(float2*)(out + (size_t)d * HD + e)       = make_float2(acc[mi][ni][0], acc[mi][ni][1]);
            *(float2*)(out + (size_t)(d + 8) * HD + e) = make_float2(acc[mi][ni][2], acc[mi][ni][3]);
        }
    }
}

// ---------------- scan (parallel) ----------------
__global__ __launch_bounds__(256) void scan_kernel(const float* __restrict__ slopes)
{
    const int gid = blockIdx.x * 256 + threadIdx.x;
    const int bh  = gid >> 14;
    const int p   = gid & 16383;
    const float bd = expf(-slopes[bh & (NH - 1)] * (float)CC);
    const size_t base = (size_t)bh * NCC * HD * HD + p;

    float st = 0.0f;
    #pragma unroll
    for (int nn = 0; nn < NCC; nn++) {
        g_kvstate[base + (size_t)nn * HD * HD] = st;
        st = bd * st + g_kvdelta[base + (size_t)nn * HD * HD];
    }
}

// ---------------- fused attention via HMMA (q,k direct from linear qkv16) ----------------
#define A_Q     0
#define A_K     34816
#define A_VT0   52224
#define A_VT1   70656
#define A_S     89088
#define A_SMEM  107520
#define A_KVS   70656

__global__ __launch_bounds__(256) void attn_mma(const float* __restrict__ slopes)
{
    extern __shared__ char smraw[];
    const uint32_t sb = smem_u32(smraw);
    __shared__ float sdec[CC];

    const int blk = blockIdx.x;
    const int itile = blockIdx.y;
    const int n  = blk & (NCC - 1);
    const int bh = blk >> 4;
    const int h  = bh & (NH - 1);
    const int b  = bh >> 4;
    const float s = slopes[h];

    const int tid = threadIdx.x, lane = tid & 31, wid = tid >> 5;
    sdec[tid] = expf(-s * (float)tid);
    const float fexp = expf(-s);

    const size_t qrow0 = (size_t)(b * SS + n * CC) * QKVN + h * HD;
    const size_t colb = (size_t)bh * HD;
    const int i0 = itile * 128;

    // group 0: q + kvsT
    #pragma unroll
    for (int it = 0; it < 8; ++it) {
        int idx = tid + 256 * it;
        int row = idx >> 4, sec = idx & 15;
        size_t g = qrow0 + (size_t)(i0 + row) * QKVN + sec * 8;
        uint32_t so = row * 272 + sec * 16;
        cpasync16(sb + A_Q + so, g_qkv16 + g);
    }
    {
        const size_t kvb = (size_t)blk * HD * HD;
        #pragma unroll
        for (int it = 0; it < 8; ++it) {
            int idx = tid + 256 * it;
            int row = idx >> 4, sec = idx & 15;
            size_t g = kvb + (size_t)row * HD + sec * 8;
            uint32_t so = row * 272 + sec * 16;
            cpasync16(sb + A_KVS + so, g_kvsT + g);
        }
    }
    cp_commit();

    // group 1: vT(j=0) into buf0
    #pragma unroll
    for (int it = 0; it < 4; ++it) {
        int idx = tid + 256 * it;
        int row = idx >> 3, sec = idx & 7;
        size_t g = (colb + row) * SS + n * CC + sec * 8;
        uint32_t so = row * 144 + sec * 16;
        cpasync16(sb + A_VT0 + so, g_vT + g);
    }
    cp_commit();

    const int wm  = (wid >> 2) * 64;
    const int wns = (wid & 3) * 16;
    const int wno = (wid & 3) * 32;
    const int erow = lane >> 2, ecol = 2 * (lane & 3);

    float oacc[4][4][4];
    #pragma unroll
    for (int mi = 0; mi < 4; ++mi)
        #pragma unroll
        for (int ni = 0; ni < 4; ++ni)
            #pragma unroll
            for (int r = 0; r < 4; ++r) oacc[mi][ni][r] = 0.0f;

    // ---- inter FIRST ----
    cp_wait<1>();
    __syncthreads();

    #pragma unroll
    for (int ks = 0; ks < 8; ++ks) {
        uint32_t aF[4][4], bF[4][2];
        const uint32_t ao = (uint32_t)(lane & 15) * 272 + (lane >> 4) * 16 + ks * 32;
        #pragma unroll
        for (int mi = 0; mi < 4; ++mi)
            ldm_x4(aF[mi], sb + A_Q + (wm + mi * 16) * 272 + ao);
        const uint32_t bo = (uint32_t)(lane & 7) * 272 + ((lane >> 3) & 1) * 16 + ks * 32;
        #pragma unroll
        for (int ni = 0; ni < 4; ++ni)
            ldm_x2(bF[ni], sb + A_KVS + (wno + ni * 8) * 272 + bo);
        #pragma unroll
        for (int mi = 0; mi < 4; ++mi)
            #pragma unroll
            for (int ni = 0; ni < 4; ++ni)
                mma16816h(oacc[mi][ni], aF[mi], bF[ni]);
    }
    #pragma unroll
    for (int mi = 0; mi < 4; ++mi) {
        const int il0 = wm + mi * 16 + erow;
        const float qd0 = sdec[i0 + il0] * fexp;
        const float qd1 = sdec[i0 + il0 + 8] * fexp;
        #pragma unroll
        for (int ni = 0; ni < 4; ++ni) {
            oacc[mi][ni][0] *= qd0;
            oacc[mi][ni][1] *= qd0;
            oacc[mi][ni][2] *= qd1;
            oacc[mi][ni][3] *= qd1;
        }
    }
    __syncthreads();

    // load k(0)
    #pragma unroll
    for (int it = 0; it < 4; ++it) {
        int idx = tid + 256 * it;
        int row = idx >> 4, sec = idx & 15;
        size_t g = qrow0 + HIDN + (size_t)row * QKVN + sec * 8;
        uint32_t so = row * 272 + sec * 16;
        cpasync16(sb + A_K + so, g_qkv16 + g);
    }
    cp_commit();

    const int njt = 2 * (itile + 1);
    for (int jt = 0; jt < njt; ++jt) {
        const int j0 = jt * 64;
        const int cur = jt & 1;
        const uint32_t vtb = sb + (cur ? A_VT1 : A_VT0);

        cp_wait<0>();
        __syncthreads();

        // ---- S = q @ k^T ----
        float sacc[4][2][4];
        #pragma unroll
        for (int mi = 0; mi < 4; ++mi)
            #pragma unroll
            for (int ni = 0; ni < 2; ++ni)
                #pragma unroll
                for (int r = 0; r < 4; ++r) sacc[mi][ni][r] = 0.0f;

        #pragma unroll
        for (int ks = 0; ks < 8; ++ks) {
            uint32_t aF[4][4], bF[2][2];
            const uint32_t ao = (uint32_t)(lane & 15) * 272 + (lane >> 4) * 16 + ks * 32;
            #pragma unroll
            for (int mi = 0; mi < 4; ++mi)
                ldm_x4(aF[mi], sb + A_Q + (wm + mi * 16) * 272 + ao);
            const uint32_t bo = (uint32_t)(lane & 7) * 272 + ((lane >> 3) & 1) * 16 + ks * 32;
            #pragma unroll
            for (int ni = 0; ni < 2; ++ni)
                ldm_x2(bF[ni], sb + A_K + (wns + ni * 8) * 272 + bo);
            #pragma unroll
            for (int mi = 0; mi < 4; ++mi)
                #pragma unroll
                for (int ni = 0; ni < 2; ++ni)
                    mma16816h(sacc[mi][ni], aF[mi], bF[ni]);
        }

        // ---- decay + store S ----
        #pragma unroll
        for (int mi = 0; mi < 4; ++mi) {
            #pragma unroll
            for (int ni = 0; ni < 2; ++ni) {
                #pragma unroll
                for (int r = 0; r < 4; ++r) {
                    int il = wm + mi * 16 + erow + (r >> 1) * 8;
                    int jl = wns + ni * 8 + ecol + (r & 1);
                    int dd = (i0 + il) - (j0 + jl);
                    float val = (dd >= 0) ? sacc[mi][ni][r] * sdec[dd] : 0.0f;
                    *(__half*)(smraw + A_S + il * 144 + jl * 2) = __float2half(val);
                }
            }
        }
        __syncthreads();

        // prefetch k(jt+1) and vT(jt+1)
        if (jt + 1 < njt) {
            const int jn = (jt + 1) * 64;
            #pragma unroll
            for (int it = 0; it < 4; ++it) {
                int idx = tid + 256 * it;
                int row = idx >> 4, sec = idx & 15;
                size_t g = qrow0 + HIDN + (size_t)(jn + row) * QKVN + sec * 8;
                uint32_t so = row * 272 + sec * 16;
                cpasync16(sb + A_K + so, g_qkv16 + g);
            }
            const uint32_t vtn = sb + (cur ? A_VT0 : A_VT1);
            #pragma unroll
            for (int it = 0; it < 4; ++it) {
                int idx = tid + 256 * it;
                int row = idx >> 3, sec = idx & 7;
                size_t g = (colb + row) * SS + n * CC + jn + sec * 8;
                uint32_t so = row * 144 + sec * 16;
                cpasync16(vtn + so, g_vT + g);
            }
            cp_commit();
        }

        // ---- O += S̃ @ v ----
        #pragma unroll
        for (int ks = 0; ks < 4; ++ks) {
            uint32_t aF[4][4], bF[4][2];
            const uint32_t ao = (uint32_t)(lane & 15) * 144 + (lane >> 4) * 16 + ks * 32;
            #pragma unroll
            for (int mi = 0; mi < 4; ++mi)
                ldm_x4(aF[mi], sb + A_S + (wm + mi * 16) * 144 + ao);
            const uint32_t bo = (uint32_t)(lane & 7) * 144 + ((lane >> 3) & 1) * 16 + ks * 32;
            #pragma unroll
            for (int ni = 0; ni < 4; ++ni)
                ldm_x2(bF[ni], vtb + (wno + ni * 8) * 144 + bo);
            #pragma unroll
            for (int mi = 0; mi < 4; ++mi)
                #pragma unroll
                for (int ni = 0; ni < 4; ++ni)
                    mma16816h(oacc[mi][ni], aF[mi], bF[ni]);
        }
    }

    // ---- epilogue: gate-fused fp16 store ----
    #pragma unroll
    for (int mi = 0; mi < 4; ++mi) {
        #pragma unroll
        for (int ni = 0; ni < 4; ++ni) {
            int il = wm + mi * 16 + erow;
            int e  = wno + ni * 8 + ecol;
            size_t o0 = (size_t)(b * SS + n * CC + i0 + il) * HIDN + h * HD + e;
            size_t o1 = o0 + 8 * HIDN;
            float2 g0 = __half22float2(*(const __half2*)(g_gate16 + o0));
            float2 g1 = __half22float2(*(const __half2*)(g_gate16 + o1));
            *(__half2*)(g_ga16 + o0) = __halves2half2(
                __float2half(oacc[mi][ni][0] * g0.x),
                __float2half(oacc[mi][ni][1] * g0.y));
            *(__half2*)(g_ga16 + o1) = __halves2half2(
                __float2half(oacc[mi][ni][2] * g1.x),
                __float2half(oacc[mi][ni][3] * g1.y));
        }
    }
}

// ---------------- launch ----------------
extern "C" void kernel_launch(void* const* d_in, const int* in_sizes, int n_in,
                              void* d_out, int out_size)
{
    const float* x      = (const float*)d_in[0];
    const float* w_qkv  = (const float*)d_in[1];
    const float* w_gate = (const float*)d_in[2];
    const float* w_out  = (const float*)d_in[3];
    const float* slopes = (const float*)d_in[4];
    float* out = (float*)d_out;

    __half *x16, *wqh, *wgh, *woh, *ga16, *qkv16, *gate16;
    cudaGetSymbolAddress((void**)&x16,    g_x16);
    cudaGetSymbolAddress((void**)&wqh,    g_wqkvT_h);
    cudaGetSymbolAddress((void**)&wgh,    g_wgateT_h);
    cudaGetSymbolAddress((void**)&woh,    g_woutT_h);
    cudaGetSymbolAddress((void**)&ga16,   g_ga16);
    cudaGetSymbolAddress((void**)&qkv16,  g_qkv16);
    cudaGetSymbolAddress((void**)&gate16, g_gate16);

    cudaFuncSetAttribute((const void*)mma_gemm_1<EPI_SILU, true>,
                         cudaFuncAttributeMaxDynamicSharedMemorySize, GEMM1_SMEM);
    cudaFuncSetAttribute((const void*)mma_gemm_1<EPI_SIGMOID, true>,
                         cudaFuncAttributeMaxDynamicSharedMemorySize, GEMM1_SMEM);
    cudaFuncSetAttribute((const void*)mma_gemm_1<EPI_NONE, false>,
                         cudaFuncAttributeMaxDynamicSharedMemorySize, GEMM1_SMEM);
    cudaFuncSetAttribute(attn_mma,
                         cudaFuncAttributeMaxDynamicSharedMemorySize, A_SMEM);
    cudaFuncSetAttribute(kvdelta_mma,
                         cudaFuncAttributeMaxDynamicSharedMemorySize, KD_SMEM);

    static cudaStream_t s2 = nullptr;
    static cudaEvent_t evA = nullptr, evB = nullptr;
    if (s2 == nullptr) {
        cudaStreamCreateWithFlags(&s2, cudaStreamNonBlocking);
        cudaEventCreateWithFlags(&evA, cudaEventDisableTiming);
        cudaEventCreateWithFlags(&evB, cudaEventDisableTiming);
    }
    const cudaStream_t s0 = (cudaStream_t)0;

    // ---- prologue (s0): x16, wqkvT, decay tables ----
    {
        int n4 = MM * HIDN / 4;
        tohalf_kernel<<<n4 / 256, 256, 0, s0>>>(x, x16, n4);
        dim3 blk(32, 8);
        transp_half_kernel<<<dim3(QKVN / 32, HIDN / 32), blk, 0, s0>>>(w_qkv, wqh, HIDN, QKVN);
        dectab_kernel<<<NH, CC, 0, s0>>>(slopes);
    }

    // ---- fork: s2 gets gate chain + q-GEMM (needs x16 + wqh) ----
    cudaEventRecord(evA, s0);
    cudaStreamWaitEvent(s2, evA, 0);
    {
        dim3 blk(32, 8);
        transp_half_kernel<<<dim3(HIDN / 32, HIDN / 32), blk, 0, s2>>>(w_gate, wgh, HIDN, HIDN);
        transp_half_kernel<<<dim3(HIDN / 32, HIDN / 32), blk, 0, s2>>>(w_out,  woh, HIDN, HIDN);
        // gate = sigmoid(x @ w_gate)
        mma_gemm_1<EPI_SIGMOID, true><<<dim3(HIDN / 256, MM / 128), 512, GEMM1_SMEM, s2>>>(
            x16, wgh, nullptr, gate16, MM, HIDN);
        // q = silu(x @ w_qkv[:, 0:2048]) -> qkv16 cols [0, 2048)
        mma_gemm_1<EPI_SILU, true><<<dim3(HIDN / 256, MM / 128), 512, GEMM1_SMEM, s2>>>(
            x16, wqh, nullptr, qkv16, MM, QKVN);
    }
    cudaEventRecord(evB, s2);

    // ---- main chain (s0) ----
    // kv = silu(x @ w_qkv[:, 2048:6144]) -> qkv16 cols [2048, 6144)
    mma_gemm_1<EPI_SILU, true><<<dim3((QKVN - HIDN) / 256, MM / 128), 512, GEMM1_SMEM, s0>>>(
        x16, wqh + (size_t)HIDN * GK, nullptr, qkv16 + HIDN, MM, QKVN);
    // kdT / vT transposes
    {
        dim3 blk(32, 8);
        trans_split_head<<<dim3(SS / 32, HD / 32, BB * NH), blk, 0, s0>>>();
    }
    // attention prep
    kvdelta_mma<<<BB * NH * NCC, 256, KD_SMEM, s0>>>();
    scan_kernel<<<BB * NH * 64, 256, 0, s0>>>(slopes);
    {
        dim3 blk(32, 8);
        kvsplitT_kernel<<<dim3(HD / 32, HD / 32, BB * NH * NCC), blk, 0, s0>>>();
    }
    // join: attn needs q (s2) + gate16 (s2)
    cudaStreamWaitEvent(s0, evB, 0);
    attn_mma<<<dim3(BB * NH * NCC, 2), 256, A_SMEM, s0>>>(slopes);
    // out = (gate*attn) @ w_out
    mma_gemm_1<EPI_NONE, false><<<dim3(HIDN / 256, MM / 128), 512, GEMM1_SMEM, s0>>>(
        ga16, woh, out, nullptr, MM, HIDN);
}

// round 17
// speedup vs baseline: 1.0235x; 1.0235x over previous
#include <cuda_runtime.h>
#include <cuda_fp16.h>
#include <math.h>
#include <stdint.h>

// ---------------- problem constants ----------------
#define BB   2
#define SS   4096
#define HIDN 2048
#define NH   16
#define HD   128
#define CC   256
#define NCC  16
#define MM   (BB*SS)          // 8192
#define QKVN (3*HIDN)         // 6144
#define GK   HIDN
#define BKC  64
#define NCHUNK (GK/BKC)       // 32

// ---------------- device scratch ----------------
__device__ float g_kvdelta[(size_t)BB*NH*NCC*HD*HD];

__device__ __half g_qkv16[(size_t)MM * QKVN];      // linear [M, 6144] fp16
__device__ __half g_x16[(size_t)MM*HIDN];
__device__ __half g_wqkvT_h[(size_t)QKVN*HIDN];
__device__ __half g_wgateT_h[(size_t)HIDN*HIDN];
__device__ __half g_woutT_h[(size_t)HIDN*HIDN];
__device__ __half g_ga16[(size_t)MM*HIDN];
__device__ __half g_gate16[(size_t)MM*HIDN];

#define PHSZ ((size_t)BB*NH*SS*HD)
__device__ __half g_kdT [PHSZ];                    // [bh][d][s]
__device__ __half g_vT  [PHSZ];                    // [bh][d][s]
__device__ __half g_kvsT[(size_t)BB*NH*NCC*HD*HD]; // [bhn][e][d']
__device__ float g_qdectab[NH*CC], g_kdectab[NH*CC];

// ---------------- epilogues ----------------
#define EPI_SILU    0
#define EPI_SIGMOID 1
#define EPI_NONE    2

__device__ __forceinline__ float apply_epi(float x, int mode) {
    if (mode == EPI_SILU)    return x / (1.0f + expf(-x));
    if (mode == EPI_SIGMOID) return 1.0f / (1.0f + expf(-x));
    return x;
}

// ---------------- base-ISA tensor-core helpers ----------------
__device__ __forceinline__ uint32_t smem_u32(const void* p) {
    uint32_t a;
    asm("{ .reg .u64 t; cvta.to.shared.u64 t, %1; cvt.u32.u64 %0, t; }" : "=r"(a) : "l"(p));
    return a;
}
__device__ __forceinline__ void cpasync16(uint32_t saddr, const void* g) {
    asm volatile("cp.async.cg.shared.global [%0], [%1], 16;" :: "r"(saddr), "l"(g));
}
__device__ __forceinline__ void cp_commit() {
    asm volatile("cp.async.commit_group;" ::: "memory");
}
template<int N> __device__ __forceinline__ void cp_wait() {
    asm volatile("cp.async.wait_group %0;" :: "n"(N) : "memory");
}
__device__ __forceinline__ void ldm_x4(uint32_t* r, uint32_t addr) {
    asm volatile("ldmatrix.sync.aligned.m8n8.x4.shared.b16 {%0,%1,%2,%3}, [%4];"
                 : "=r"(r[0]), "=r"(r[1]), "=r"(r[2]), "=r"(r[3]) : "r"(addr));
}
__device__ __forceinline__ void ldm_x2(uint32_t* r, uint32_t addr) {
    asm volatile("ldmatrix.sync.aligned.m8n8.x2.shared.b16 {%0,%1}, [%2];"
                 : "=r"(r[0]), "=r"(r[1]) : "r"(addr));
}
__device__ __forceinline__ void mma16816h(float* c, const uint32_t* a, const uint32_t* b) {
    asm volatile(
        "mma.sync.aligned.m16n8k16.row.col.f32.f16.f16.f32 "
        "{%0,%1,%2,%3},{%4,%5,%6,%7},{%8,%9},{%0,%1,%2,%3};"
        : "+f"(c[0]), "+f"(c[1]), "+f"(c[2]), "+f"(c[3])
        : "r"(a[0]), "r"(a[1]), "r"(a[2]), "r"(a[3]), "r"(b[0]), "r"(b[1]));
}

#define LDSW   144

// ---------------- fp16 1-pass GEMM: tile 128x256, 512 thr ----------------
#define HA_SZ  (128 * LDSW)               // 18432
#define HB_SZ  (256 * LDSW)               // 36864
#define H1BUF  (HA_SZ + HB_SZ)            // 55296
#define GEMM1_SMEM (2 * H1BUF)            // 110592

template<int EPI, bool OUT16>
__global__ __launch_bounds__(512) void mma_gemm_1(
    const __half* __restrict__ A, const __half* __restrict__ Bh,
    float* __restrict__ Cf, __half* __restrict__ Ch, int M, int N)
{
    extern __shared__ char smraw[];
    const uint32_t sb = smem_u32(smraw);

    const int tid  = threadIdx.x;
    const int lane = tid & 31;
    const int wid  = tid >> 5;
    const int bm = blockIdx.y * 128;
    const int bn = blockIdx.x * 256;
    const int wm = (wid >> 3) * 64;
    const int wn = (wid & 7) * 32;

    auto prefetch = [&](int c, int buf) {
        const uint32_t bbase = sb + buf * H1BUF;
        const int k0 = c * BKC;
        #pragma unroll
        for (int i = 0; i < 2; ++i) {
            int idx = tid + 512 * i;
            int row = idx >> 3, sec = idx & 7;
            const uint32_t so = row * LDSW + sec * 16;
            const size_t ga = (size_t)(bm + row) * GK + k0 + sec * 8;
            cpasync16(bbase + so, A + ga);
        }
        #pragma unroll
        for (int i = 0; i < 4; ++i) {
            int idx = tid + 512 * i;
            int row = idx >> 3, sec = idx & 7;
            const uint32_t so = row * LDSW + sec * 16;
            const size_t gb = (size_t)(bn + row) * GK + k0 + sec * 8;
            cpasync16(bbase + HA_SZ + so, Bh + gb);
        }
        cp_commit();
    };

    float acc[4][4][4];
    #pragma unroll
    for (int mi = 0; mi < 4; ++mi)
        #pragma unroll
        for (int ni = 0; ni < 4; ++ni)
            #pragma unroll
            for (int r = 0; r < 4; ++r) acc[mi][ni][r] = 0.0f;

    const uint32_t aOff = (uint32_t)(wm + (lane & 15)) * LDSW + (lane >> 4) * 16;
    const uint32_t bOff = (uint32_t)(wn + (lane & 7))  * LDSW + ((lane >> 3) & 1) * 16;

    prefetch(0, 0);

    for (int c = 0; c < NCHUNK; ++c) {
        const int cur = c & 1;
        if (c + 1 < NCHUNK) prefetch(c + 1, cur ^ 1);
        if (c + 1 < NCHUNK) cp_wait<1>(); else cp_wait<0>();
        __syncthreads();

        const uint32_t bbase = sb + cur * H1BUF;
        #pragma unroll
        for (int ks = 0; ks < 4; ++ks) {
            const uint32_t kso = ks * 32;
            uint32_t aF[4][4], bF[4][2];
            #pragma unroll
            for (int mi = 0; mi < 4; ++mi)
                ldm_x4(aF[mi], bbase + aOff + mi * 16 * LDSW + kso);
            #pragma unroll
            for (int ni = 0; ni < 4; ++ni)
                ldm_x2(bF[ni], bbase + HA_SZ + bOff + ni * 8 * LDSW + kso);
            #pragma unroll
            for (int mi = 0; mi < 4; ++mi)
                #pragma unroll
                for (int ni = 0; ni < 4; ++ni)
                    mma16816h(acc[mi][ni], aF[mi], bF[ni]);
        }
        __syncthreads();
    }

    const int erow = lane >> 2;
    const int ecol = 2 * (lane & 3);
    #pragma unroll
    for (int mi = 0; mi < 4; ++mi) {
        #pragma unroll
        for (int ni = 0; ni < 4; ++ni) {
            const int gr0 = bm + wm + mi * 16 + erow;
            const int gc  = bn + wn + ni * 8 + ecol;
            float v0 = apply_epi(acc[mi][ni][0], EPI);
            float v1 = apply_epi(acc[mi][ni][1], EPI);
            float v2 = apply_epi(acc[mi][ni][2], EPI);
            float v3 = apply_epi(acc[mi][ni][3], EPI);
            if (OUT16) {
                size_t o0 = (size_t)gr0 * N + gc;
                *(__half2*)(Ch + o0) =
                    __halves2half2(__float2half(v0), __float2half(v1));
                *(__half2*)(Ch + o0 + 8 * (size_t)N) =
                    __halves2half2(__float2half(v2), __float2half(v3));
            } else {
                *(float2*)(Cf + (size_t)gr0 * N + gc)       = make_float2(v0, v1);
                *(float2*)(Cf + (size_t)(gr0 + 8) * N + gc) = make_float2(v2, v3);
            }
        }
    }
}

// ---------------- conversion kernels ----------------
__device__ __forceinline__ void store4h(__half* d, size_t o, float4 v)
{
    *(__half2*)(d + o)     = __halves2half2(__float2half(v.x), __float2half(v.y));
    *(__half2*)(d + o + 2) = __halves2half2(__float2half(v.z), __float2half(v.w));
}

__global__ __launch_bounds__(256) void tohalf_kernel(
    const float* __restrict__ in, __half* __restrict__ d16, int n4)
{
    int i = blockIdx.x * 256 + threadIdx.x;
    if (i >= n4) return;
    store4h(d16, (size_t)i * 4, ((const float4*)in)[i]);
}

__global__ void transp_half_kernel(
    const float* __restrict__ w, __half* __restrict__ t, int K, int N)
{
    __shared__ float ts[32][33];
    const int n0 = blockIdx.x * 32, k0 = blockIdx.y * 32;
    const int x = threadIdx.x, y = threadIdx.y;
    #pragma unroll
    for (int r = 0; r < 32; r += 8)
        ts[y + r][x] = w[(size_t)(k0 + y + r) * N + n0 + x];
    __syncthreads();
    #pragma unroll
    for (int r = 0; r < 32; r += 8) {
        size_t o = (size_t)(n0 + y + r) * K + k0 + x;
        t[o] = __float2half(ts[x][y + r]);
    }
}

__global__ void dectab_kernel(const float* __restrict__ slopes)
{
    int h = blockIdx.x, i = threadIdx.x;
    float s = slopes[h];
    g_qdectab[h * CC + i] = expf(-s * (float)(i + 1));
    g_kdectab[h * CC + i] = expf(-s * (float)(CC - 1 - i));
}

// g_qkv16 k,v -> kdT (decayed), vT [bh][d][s] fp16
__global__ void trans_split_head()
{
    __shared__ float tk[32][33], tv[32][33];
    const int z  = blockIdx.z;
    const int b  = z >> 4, h = z & 15;
    const int s0 = blockIdx.x * 32;
    const int d0 = blockIdx.y * 32;
    const int x = threadIdx.x, y = threadIdx.y;

    #pragma unroll
    for (int r = 0; r < 32; r += 8) {
        size_t base = (size_t)(b * SS + s0 + y + r) * QKVN + h * HD + d0 + x;
        tk[y + r][x] = __half2float(g_qkv16[base + HIDN]);
        tv[y + r][x] = __half2float(g_qkv16[base + 2 * HIDN]);
    }
    __syncthreads();
    #pragma unroll
    for (int r = 0; r < 32; r += 8) {
        int d = d0 + y + r;
        int s = s0 + x;
        float kdec = g_kdectab[h * CC + (s & (CC - 1))];
        size_t o = ((size_t)z * HD + d) * SS + s;
        g_kdT[o] = __float2half(tk[x][y + r] * kdec);
        g_vT[o]  = __float2half(tv[x][y + r]);
    }
}

// ---------------- kvdelta via HMMA (fp16 1-pass, double-buffered) ----------------
#define KD_MAT  18432
#define KD_BUF  (2 * KD_MAT)          // 36864
#define KD_SMEM (2 * KD_BUF)          // 73728

__global__ __launch_bounds__(256) void kvdelta_mma()
{
    extern __shared__ char smraw[];
    const uint32_t sb = smem_u32(smraw);

    const int blk = blockIdx.x;
    const int n  = blk & (NCC - 1);
    const int bh = blk >> 4;
    const size_t colb = (size_t)bh * HD;

    const int tid = threadIdx.x, lane = tid & 31, wid = tid >> 5;
    const int wm = (wid >> 2) * 64;
    const int wn = (wid & 3) * 32;

    auto prefetch = [&](int kt, int buf) {
        const uint32_t bbase = sb + buf * KD_BUF;
        const int k0 = n * CC + kt * 64;
        #pragma unroll
        for (int it = 0; it < 4; ++it) {
            int idx = tid + 256 * it;
            int row = idx >> 3, sec = idx & 7;
            size_t g = (colb + row) * SS + k0 + sec * 8;
            uint32_t so = row * 144 + sec * 16;
            cpasync16(bbase + 0 * KD_MAT + so, g_kdT + g);
            cpasync16(bbase + 1 * KD_MAT + so, g_vT + g);
        }
        cp_commit();
    };

    float acc[4][4][4];
    #pragma unroll
    for (int mi = 0; mi < 4; ++mi)
        #pragma unroll
        for (int ni = 0; ni < 4; ++ni)
            #pragma unroll
            for (int r = 0; r < 4; ++r) acc[mi][ni][r] = 0.0f;

    prefetch(0, 0);

    for (int kt = 0; kt < 4; ++kt) {
        const int cur = kt & 1;
        if (kt + 1 < 4) prefetch(kt + 1, cur ^ 1);
        if (kt + 1 < 4) cp_wait<1>(); else cp_wait<0>();
        __syncthreads();

        const uint32_t bbase = sb + cur * KD_BUF;
        #pragma unroll
        for (int ks = 0; ks < 4; ++ks) {
            uint32_t aF[4][4], bF[4][2];
            const uint32_t ao = (uint32_t)(lane & 15) * 144 + (lane >> 4) * 16 + ks * 32;
            #pragma unroll
            for (int mi = 0; mi < 4; ++mi)
                ldm_x4(aF[mi], bbase + 0 * KD_MAT + (wm + mi * 16) * 144 + ao);
            const uint32_t bo = (uint32_t)(lane & 7) * 144 + ((lane >> 3) & 1) * 16 + ks * 32;
            #pragma unroll
            for (int ni = 0; ni < 4; ++ni)
                ldm_x2(bF[ni], bbase + 1 * KD_MAT + (wn + ni * 8) * 144 + bo);
            #pragma unroll
            for (int mi = 0; mi < 4; ++mi)
                #pragma unroll
                for (int ni = 0; ni < 4; ++ni)
                    mma16816h(acc[mi][ni], aF[mi], bF[ni]);
        }
        __syncthreads();
    }

    const int erow = lane >> 2, ecol = 2 * (lane & 3);
    float* out = &g_kvdelta[(size_t)blk * HD * HD];
    #pragma unroll
    for (int mi = 0; mi < 4; ++mi) {
        #pragma unroll
        for (int ni = 0; ni < 4; ++ni) {
            int d = wm + mi * 16 + erow;
            int e = wn + ni * 8 + ecol;
            *(float2*)(out + (size_t)d * HD + e)       = make_float2(acc[mi][ni][0], acc[mi][ni][1]);
            *(float2*)(out + (size_t)(d + 8) * HD + e) = make_float2(acc[mi][ni][2], acc[mi][ni][3]);
        }
    }
}

// ---------------- fused scan + transpose: kvsT[bhn][e][d] = fp16(state before chunk n) ----------------
// grid (4, 4, BB*NH), block (32, 8). Each block owns a 32x32 (d,e) tile of one bh.
__global__ void scan_fused_kernel(const float* __restrict__ slopes)
{
    __shared__ float t[32][33];
    const int bh = blockIdx.z;
    const int d0 = blockIdx.x * 32;
    const int e0 = blockIdx.y * 32;
    const int x = threadIdx.x, y = threadIdx.y;
    const float bd = expf(-slopes[bh & (NH - 1)] * (float)CC);
    const size_t base = (size_t)bh * NCC * HD * HD;

    float st[4] = {0.0f, 0.0f, 0.0f, 0.0f};
    for (int nn = 0; nn < NCC; ++nn) {
        const size_t cb = base + (size_t)nn * HD * HD;
        // stage pre-state into smem: t[d_local][e_local]
        #pragma unroll
        for (int r = 0; r < 4; ++r)
            t[y + 8 * r][x] = st[r];
        __syncthreads();
        // transposed fp16 write: kvsT[bhn][e][d]
        #pragma unroll
        for (int r = 0; r < 4; ++r) {
            size_t o = cb + (size_t)(e0 + y + 8 * r) * HD + d0 + x;
            g_kvsT[o] = __float2half(t[x][y + 8 * r]);
        }
        __syncthreads();
        // recurrence: st = bd*st + kvdelta[nn]  (coalesced fp32 read)
        #pragma unroll
        for (int r = 0; r < 4; ++r)
            st[r] = bd * st[r] +
                    g_kvdelta[cb + (size_t)(d0 + y + 8 * r) * HD + e0 + x];
    }
}

// ---------------- fused attention via HMMA (q,k direct from linear qkv16) ----------------
#define A_Q     0
#define A_K     34816
#define A_VT0   52224
#define A_VT1   70656
#define A_S     89088
#define A_SMEM  107520
#define A_KVS   70656

__global__ __launch_bounds__(256) void attn_mma(const float* __restrict__ slopes)
{
    extern __shared__ char smraw[];
    const uint32_t sb = smem_u32(smraw);
    __shared__ float sdec[CC];

    const int blk = blockIdx.x;
    const int itile = blockIdx.y;
    const int n  = blk & (NCC - 1);
    const int bh = blk >> 4;
    const int h  = bh & (NH - 1);
    const int b  = bh >> 4;
    const float s = slopes[h];

    const int tid = threadIdx.x, lane = tid & 31, wid = tid >> 5;
    sdec[tid] = expf(-s * (float)tid);
    const float fexp = expf(-s);

    const size_t qrow0 = (size_t)(b * SS + n * CC) * QKVN + h * HD;
    const size_t colb = (size_t)bh * HD;
    const int i0 = itile * 128;

    // group 0: q + kvsT
    #pragma unroll
    for (int it = 0; it < 8; ++it) {
        int idx = tid + 256 * it;
        int row = idx >> 4, sec = idx & 15;
        size_t g = qrow0 + (size_t)(i0 + row) * QKVN + sec * 8;
        uint32_t so = row * 272 + sec * 16;
        cpasync16(sb + A_Q + so, g_qkv16 + g);
    }
    {
        const size_t kvb = (size_t)blk * HD * HD;
        #pragma unroll
        for (int it = 0; it < 8; ++it) {
            int idx = tid + 256 * it;
            int row = idx >> 4, sec = idx & 15;
            size_t g = kvb + (size_t)row * HD + sec * 8;
            uint32_t so = row * 272 + sec * 16;
            cpasync16(sb + A_KVS + so, g_kvsT + g);
        }
    }
    cp_commit();

    // group 1: vT(j=0) into buf0
    #pragma unroll
    for (int it = 0; it < 4; ++it) {
        int idx = tid + 256 * it;
        int row = idx >> 3, sec = idx & 7;
        size_t g = (colb + row) * SS + n * CC + sec * 8;
        uint32_t so = row * 144 + sec * 16;
        cpasync16(sb + A_VT0 + so, g_vT + g);
    }
    cp_commit();

    const int wm  = (wid >> 2) * 64;
    const int wns = (wid & 3) * 16;
    const int wno = (wid & 3) * 32;
    const int erow = lane >> 2, ecol = 2 * (lane & 3);

    float oacc[4][4][4];
    #pragma unroll
    for (int mi = 0; mi < 4; ++mi)
        #pragma unroll
        for (int ni = 0; ni < 4; ++ni)
            #pragma unroll
            for (int r = 0; r < 4; ++r) oacc[mi][ni][r] = 0.0f;

    // ---- inter FIRST ----
    cp_wait<1>();
    __syncthreads();

    #pragma unroll
    for (int ks = 0; ks < 8; ++ks) {
        uint32_t aF[4][4], bF[4][2];
        const uint32_t ao = (uint32_t)(lane & 15) * 272 + (lane >> 4) * 16 + ks * 32;
        #pragma unroll
        for (int mi = 0; mi < 4; ++mi)
            ldm_x4(aF[mi], sb + A_Q + (wm + mi * 16) * 272 + ao);
        const uint32_t bo = (uint32_t)(lane & 7) * 272 + ((lane >> 3) & 1) * 16 + ks * 32;
        #pragma unroll
        for (int ni = 0; ni < 4; ++ni)
            ldm_x2(bF[ni], sb + A_KVS + (wno + ni * 8) * 272 + bo);
        #pragma unroll
        for (int mi = 0; mi < 4; ++mi)
            #pragma unroll
            for (int ni = 0; ni < 4; ++ni)
                mma16816h(oacc[mi][ni], aF[mi], bF[ni]);
    }
    #pragma unroll
    for (int mi = 0; mi < 4; ++mi) {
        const int il0 = wm + mi * 16 + erow;
        const float qd0 = sdec[i0 + il0] * fexp;
        const float qd1 = sdec[i0 + il0 + 8] * fexp;
        #pragma unroll
        for (int ni = 0; ni < 4; ++ni) {
            oacc[mi][ni][0] *= qd0;
            oacc[mi][ni][1] *= qd0;
            oacc[mi][ni][2] *= qd1;
            oacc[mi][ni][3] *= qd1;
        }
    }
    __syncthreads();

    // load k(0)
    #pragma unroll
    for (int it = 0; it < 4; ++it) {
        int idx = tid + 256 * it;
        int row = idx >> 4, sec = idx & 15;
        size_t g = qrow0 + HIDN + (size_t)row * QKVN + sec * 8;
        uint32_t so = row * 272 + sec * 16;
        cpasync16(sb + A_K + so, g_qkv16 + g);
    }
    cp_commit();

    const int njt = 2 * (itile + 1);
    for (int jt = 0; jt < njt; ++jt) {
        const int j0 = jt * 64;
        const int cur = jt & 1;
        const uint32_t vtb = sb + (cur ? A_VT1 : A_VT0);

        cp_wait<0>();
        __syncthreads();

        // ---- S = q @ k^T ----
        float sacc[4][2][4];
        #pragma unroll
        for (int mi = 0; mi < 4; ++mi)
            #pragma unroll
            for (int ni = 0; ni < 2; ++ni)
                #pragma unroll
                for (int r = 0; r < 4; ++r) sacc[mi][ni][r] = 0.0f;

        #pragma unroll
        for (int ks = 0; ks < 8; ++ks) {
            uint32_t aF[4][4], bF[2][2];
            const uint32_t ao = (uint32_t)(lane & 15) * 272 + (lane >> 4) * 16 + ks * 32;
            #pragma unroll
            for (int mi = 0; mi < 4; ++mi)
                ldm_x4(aF[mi], sb + A_Q + (wm + mi * 16) * 272 + ao);
            const uint32_t bo = (uint32_t)(lane & 7) * 272 + ((lane >> 3) & 1) * 16 + ks * 32;
            #pragma unroll
            for (int ni = 0; ni < 2; ++ni)
                ldm_x2(bF[ni], sb + A_K + (wns + ni * 8) * 272 + bo);
            #pragma unroll
            for (int mi = 0; mi < 4; ++mi)
                #pragma unroll
                for (int ni = 0; ni < 2; ++ni)
                    mma16816h(sacc[mi][ni], aF[mi], bF[ni]);
        }

        // ---- decay + store S ----
        #pragma unroll
        for (int mi = 0; mi < 4; ++mi) {
            #pragma unroll
            for (int ni = 0; ni < 2; ++ni) {
                #pragma unroll
                for (int r = 0; r < 4; ++r) {
                    int il = wm + mi * 16 + erow + (r >> 1) * 8;
                    int jl = wns + ni * 8 + ecol + (r & 1);
                    int dd = (i0 + il) - (j0 + jl);
                    float val = (dd >= 0) ? sacc[mi][ni][r] * sdec[dd] : 0.0f;
                    *(__half*)(smraw + A_S + il * 144 + jl * 2) = __float2half(val);
                }
            }
        }
        __syncthreads();

        // prefetch k(jt+1) and vT(jt+1)
        if (jt + 1 < njt) {
            const int jn = (jt + 1) * 64;
            #pragma unroll
            for (int it = 0; it < 4; ++it) {
                int idx = tid + 256 * it;
                int row = idx >> 4, sec = idx & 15;
                size_t g = qrow0 + HIDN + (size_t)(jn + row) * QKVN + sec * 8;
                uint32_t so = row * 272 + sec * 16;
                cpasync16(sb + A_K + so, g_qkv16 + g);
            }
            const uint32_t vtn = sb + (cur ? A_VT0 : A_VT1);
            #pragma unroll
            for (int it = 0; it < 4; ++it) {
                int idx = tid + 256 * it;
                int row = idx >> 3, sec = idx & 7;
                size_t g = (colb + row) * SS + n * CC + jn + sec * 8;
                uint32_t so = row * 144 + sec * 16;
                cpasync16(vtn + so, g_vT + g);
            }
            cp_commit();
        }

        // ---- O += S̃ @ v ----
        #pragma unroll
        for (int ks = 0; ks < 4; ++ks) {
            uint32_t aF[4][4], bF[4][2];
            const uint32_t ao = (uint32_t)(lane & 15) * 144 + (lane >> 4) * 16 + ks * 32;
            #pragma unroll
            for (int mi = 0; mi < 4; ++mi)
                ldm_x4(aF[mi], sb + A_S + (wm + mi * 16) * 144 + ao);
            const uint32_t bo = (uint32_t)(lane & 7) * 144 + ((lane >> 3) & 1) * 16 + ks * 32;
            #pragma unroll
            for (int ni = 0; ni < 4; ++ni)
                ldm_x2(bF[ni], vtb + (wno + ni * 8) * 144 + bo);
            #pragma unroll
            for (int mi = 0; mi < 4; ++mi)
                #pragma unroll
                for (int ni = 0; ni < 4; ++ni)
                    mma16816h(oacc[mi][ni], aF[mi], bF[ni]);
        }
    }

    // ---- epilogue: gate-fused fp16 store ----
    #pragma unroll
    for (int mi = 0; mi < 4; ++mi) {
        #pragma unroll
        for (int ni = 0; ni < 4; ++ni) {
            int il = wm + mi * 16 + erow;
            int e  = wno + ni * 8 + ecol;
            size_t o0 = (size_t)(b * SS + n * CC + i0 + il) * HIDN + h * HD + e;
            size_t o1 = o0 + 8 * HIDN;
            float2 g0 = __half22float2(*(const __half2*)(g_gate16 + o0));
            float2 g1 = __half22float2(*(const __half2*)(g_gate16 + o1));
            *(__half2*)(g_ga16 + o0) = __halves2half2(
                __float2half(oacc[mi][ni][0] * g0.x),
                __float2half(oacc[mi][ni][1] * g0.y));
            *(__half2*)(g_ga16 + o1) = __halves2half2(
                __float2half(oacc[mi][ni][2] * g1.x),
                __float2half(oacc[mi][ni][3] * g1.y));
        }
    }
}

// ---------------- launch ----------------
extern "C" void kernel_launch(void* const* d_in, const int* in_sizes, int n_in,
                              void* d_out, int out_size)
{
    const float* x      = (const float*)d_in[0];
    const float* w_qkv  = (const float*)d_in[1];
    const float* w_gate = (const float*)d_in[2];
    const float* w_out  = (const float*)d_in[3];
    const float* slopes = (const float*)d_in[4];
    float* out = (float*)d_out;

    __half *x16, *wqh, *wgh, *woh, *ga16, *qkv16, *gate16;
    cudaGetSymbolAddress((void**)&x16,    g_x16);
    cudaGetSymbolAddress((void**)&wqh,    g_wqkvT_h);
    cudaGetSymbolAddress((void**)&wgh,    g_wgateT_h);
    cudaGetSymbolAddress((void**)&woh,    g_woutT_h);
    cudaGetSymbolAddress((void**)&ga16,   g_ga16);
    cudaGetSymbolAddress((void**)&qkv16,  g_qkv16);
    cudaGetSymbolAddress((void**)&gate16, g_gate16);

    cudaFuncSetAttribute((const void*)mma_gemm_1<EPI_SILU, true>,
                         cudaFuncAttributeMaxDynamicSharedMemorySize, GEMM1_SMEM);
    cudaFuncSetAttribute((const void*)mma_gemm_1<EPI_SIGMOID, true>,
                         cudaFuncAttributeMaxDynamicSharedMemorySize, GEMM1_SMEM);
    cudaFuncSetAttribute((const void*)mma_gemm_1<EPI_NONE, false>,
                         cudaFuncAttributeMaxDynamicSharedMemorySize, GEMM1_SMEM);
    cudaFuncSetAttribute(attn_mma,
                         cudaFuncAttributeMaxDynamicSharedMemorySize, A_SMEM);
    cudaFuncSetAttribute(kvdelta_mma,
                         cudaFuncAttributeMaxDynamicSharedMemorySize, KD_SMEM);

    static cudaStream_t s2 = nullptr;
    static cudaEvent_t evA = nullptr, evX = nullptr, evW = nullptr, evB = nullptr;
    if (s2 == nullptr) {
        cudaStreamCreateWithFlags(&s2, cudaStreamNonBlocking);
        cudaEventCreateWithFlags(&evA, cudaEventDisableTiming);
        cudaEventCreateWithFlags(&evX, cudaEventDisableTiming);
        cudaEventCreateWithFlags(&evW, cudaEventDisableTiming);
        cudaEventCreateWithFlags(&evB, cudaEventDisableTiming);
    }
    const cudaStream_t s0 = (cudaStream_t)0;

    // ---- fork at entry: s2 does weight prep (independent of x) ----
    cudaEventRecord(evA, s0);
    cudaStreamWaitEvent(s2, evA, 0);
    {
        dim3 blk(32, 8);
        dectab_kernel<<<NH, CC, 0, s2>>>(slopes);
        transp_half_kernel<<<dim3(QKVN / 32, HIDN / 32), blk, 0, s2>>>(w_qkv, wqh, HIDN, QKVN);
        cudaEventRecord(evW, s2);           // wqh + dectab ready
        transp_half_kernel<<<dim3(HIDN / 32, HIDN / 32), blk, 0, s2>>>(w_gate, wgh, HIDN, HIDN);
        transp_half_kernel<<<dim3(HIDN / 32, HIDN / 32), blk, 0, s2>>>(w_out,  woh, HIDN, HIDN);
    }

    // ---- s0: x conversion ----
    {
        int n4 = MM * HIDN / 4;
        tohalf_kernel<<<n4 / 256, 256, 0, s0>>>(x, x16, n4);
    }
    cudaEventRecord(evX, s0);               // x16 ready

    // ---- s2: gate GEMM (needs x16 + wgh) ----
    cudaStreamWaitEvent(s2, evX, 0);
    mma_gemm_1<EPI_SIGMOID, true><<<dim3(HIDN / 256, MM / 128), 512, GEMM1_SMEM, s2>>>(
        x16, wgh, nullptr, gate16, MM, HIDN);
    cudaEventRecord(evB, s2);               // gate16 + woh ready

    // ---- s0 main chain ----
    cudaStreamWaitEvent(s0, evW, 0);
    // qkv = silu(x @ w_qkv) -> fp16 linear
    mma_gemm_1<EPI_SILU, true><<<dim3(QKVN / 256, MM / 128), 512, GEMM1_SMEM, s0>>>(
        x16, wqh, nullptr, qkv16, MM, QKVN);
    // kdT / vT transposes
    {
        dim3 blk(32, 8);
        trans_split_head<<<dim3(SS / 32, HD / 32, BB * NH), blk, 0, s0>>>();
    }
    // attention prep
    kvdelta_mma<<<BB * NH * NCC, 256, KD_SMEM, s0>>>();
    {
        dim3 blk(32, 8);
        scan_fused_kernel<<<dim3(HD / 32, HD / 32, BB * NH), blk, 0, s0>>>(slopes);
    }
    // join: attn needs gate16 (s2)
    cudaStreamWaitEvent(s0, evB, 0);
    attn_mma<<<dim3(BB * NH * NCC, 2), 256, A_SMEM, s0>>>(slopes);
    // out = (gate*attn) @ w_out
    mma_gemm_1<EPI_NONE, false><<<dim3(HIDN / 256, MM / 128), 512, GEMM1_SMEM, s0>>>(
        ga16, woh, out, nullptr, MM, HIDN);
}